// round 12
// baseline (speedup 1.0000x reference)
#include <cuda_runtime.h>

// ChunkedValueCrossAttn: softmax over a single context token == 1.0, so
// y[b,c,h,w] = (Wo @ (Wv @ context[b]))[c] + bo[c] — a constant per (b,c)
// broadcast over HxW. x/Wq/Wk are dead inputs.
//
// out: [2, 64, 1024, 1024] f32 = 536.9 MB write-only -> HBM store-bound.
//
// Fused, barrier-free, shared-free. Every warp redundantly computes its
// block's constant via the reassociation y = bo[c] + (Wo[c,:] @ Wv) . ctx:
// lane l owns (rows 8t+(l>>2), ctx-quarter l&3) — a perfect partition of the
// 32x16 double sum — so ONE 5-shfl butterfly finishes the reduction.
// Serial shfl depth 6 (was 11 in round 11), shfl count 9 (was 17).
// Loads stay fully coalesced (4x LDG.128 Wv + 1 ctx + 1 Wo + uniform bo).
// Store shape: measured-best 16384 blocks x 256 thr x 8 f4/thread.

#define B_       2
#define CQ_      64
#define INNER_   32
#define CTX_     16
#define TPB_     256
#define F4_PER_THREAD_ 8
#define F4_PER_BLOCK_  (TPB_ * F4_PER_THREAD_)   // 2048 float4 = 32KB

__global__ void __launch_bounds__(TPB_) fused_fill_kernel(
        float4* __restrict__ out,
        const float* __restrict__ context,
        const float* __restrict__ Wv,
        const float* __restrict__ Wo,
        const float* __restrict__ bo) {
    unsigned int slab = blockIdx.x >> 7;       // 128 blocks per slab
    unsigned int b = slab >> 6;                // batch index
    unsigned int c = slab & 63u;               // channel index

    const unsigned FULL = 0xFFFFFFFFu;
    int l = threadIdx.x & 31;

    // ctx quarter for this lane: context[b] is 16 floats = 4 float4.
    float4 ctxq = ((const float4*)context)[b * 4 + (l & 3)];
    float wo_l  = Wo[c * INNER_ + l];          // lane l holds Wo[c,l], coalesced
    float bias  = bo[c];                       // uniform broadcast

    // Wv: 32 rows x 16 floats = 128 float4. Iter t, lane l loads float4
    // idx = 32t+l -> row 8t+(l>>2), quarter l&3. Coalesced 512B per iter.
    // acc4 += Wo[c, row] * Wv4[row, quarter]; the 4 shfl pulls of woc are
    // mutually independent (no chain).
    const float4* Wv4 = (const float4*)Wv;
    float4 acc4 = make_float4(0.f, 0.f, 0.f, 0.f);
    #pragma unroll
    for (int t = 0; t < 4; ++t) {
        float4 w  = Wv4[t * 32 + l];
        float woc = __shfl_sync(FULL, wo_l, 8 * t + (l >> 2));
        acc4.x += woc * w.x;
        acc4.y += woc * w.y;
        acc4.z += woc * w.z;
        acc4.w += woc * w.w;
    }

    // Per-lane scalar partial, then ONE butterfly over all 32 lanes:
    // each (row, quarter) pair is covered exactly once across the warp.
    float s = acc4.x * ctxq.x + acc4.y * ctxq.y
            + acc4.z * ctxq.z + acc4.w * ctxq.w;
    #pragma unroll
    for (int off = 16; off > 0; off >>= 1)
        s += __shfl_xor_sync(FULL, s, off);    // full sum in ALL lanes

    float val = s + bias;

    float4 f = make_float4(val, val, val, val);
    unsigned int base = blockIdx.x * (unsigned)F4_PER_BLOCK_ + threadIdx.x;
    #pragma unroll
    for (int k = 0; k < F4_PER_THREAD_; ++k)
        out[base + k * (unsigned)TPB_] = f;
}

extern "C" void kernel_launch(void* const* d_in, const int* in_sizes, int n_in,
                              void* d_out, int out_size) {
    // metadata order: x, context, Wq, Wk, Wv, Wo, bo
    const float* context = (const float*)d_in[1];
    const float* Wv      = (const float*)d_in[4];
    const float* Wo      = (const float*)d_in[5];
    const float* bo      = (const float*)d_in[6];

    // out_size = 134,217,728 floats = 33,554,432 float4 -> 16384 blocks exact
    int n4 = out_size / 4;
    int blocks = n4 / F4_PER_BLOCK_;   // 16384
    fused_fill_kernel<<<blocks, TPB_>>>((float4*)d_out, context, Wv, Wo, bo);
}

// round 13
// speedup vs baseline: 1.0055x; 1.0055x over previous
#include <cuda_runtime.h>

// ChunkedValueCrossAttn: softmax over a single context token == 1.0, so
// y[b,c,h,w] = (Wo @ (Wv @ context[b]))[c] + bo[c] — a constant per (b,c)
// broadcast over HxW. x/Wq/Wk are dead inputs.
//
// out: [2, 64, 1024, 1024] f32 = 536.9 MB write-only -> HBM store-bound.
//
// Round-12 kernel (best: 74.02us, DRAM 81.4%) with one change: 256-bit
// stores (st.global.v8.f32, sm_100a+). 4x STG.256 per thread instead of
// 8x STG.128 — half the store instructions / L1tex dispatches, shorter
// per-warp store epilogue. Prologue unchanged: barrier-free reassociated
// warp-redundant constant compute, y = bo[c] + (Wo[c,:] @ Wv) . ctx,
// coalesced loads, one 5-shfl butterfly.

#define B_       2
#define CQ_      64
#define INNER_   32
#define CTX_     16
#define TPB_     256
#define F8_PER_THREAD_ 4                          // 4 x 32B = 128B per thread
#define FLOATS_PER_BLOCK_ (TPB_ * F8_PER_THREAD_ * 8)   // 8192 floats = 32KB

__device__ __forceinline__ void stg256(float* p, float v) {
    asm volatile(
        "st.global.v8.f32 [%0], {%1, %2, %3, %4, %5, %6, %7, %8};"
        :: "l"(p), "f"(v), "f"(v), "f"(v), "f"(v),
                   "f"(v), "f"(v), "f"(v), "f"(v)
        : "memory");
}

__global__ void __launch_bounds__(TPB_) fused_fill_kernel(
        float* __restrict__ out,
        const float* __restrict__ context,
        const float* __restrict__ Wv,
        const float* __restrict__ Wo,
        const float* __restrict__ bo) {
    unsigned int slab = blockIdx.x >> 7;       // 128 blocks per 4MB slab
    unsigned int b = slab >> 6;                // batch index
    unsigned int c = slab & 63u;               // channel index

    const unsigned FULL = 0xFFFFFFFFu;
    int l = threadIdx.x & 31;

    // ctx quarter for this lane: context[b] is 16 floats = 4 float4.
    float4 ctxq = ((const float4*)context)[b * 4 + (l & 3)];
    float wo_l  = Wo[c * INNER_ + l];          // lane l holds Wo[c,l], coalesced
    float bias  = bo[c];                       // uniform broadcast

    // Wv: 32 rows x 16 floats = 128 float4. Iter t, lane l loads float4
    // idx = 32t+l -> row 8t+(l>>2), quarter l&3. Coalesced 512B per iter.
    const float4* Wv4 = (const float4*)Wv;
    float4 acc4 = make_float4(0.f, 0.f, 0.f, 0.f);
    #pragma unroll
    for (int t = 0; t < 4; ++t) {
        float4 w  = Wv4[t * 32 + l];
        float woc = __shfl_sync(FULL, wo_l, 8 * t + (l >> 2));
        acc4.x += woc * w.x;
        acc4.y += woc * w.y;
        acc4.z += woc * w.z;
        acc4.w += woc * w.w;
    }

    // Per-lane partial covers (rows 8t+(l>>2), quarter l&3) exactly once
    // across the warp -> ONE butterfly finishes the double sum.
    float s = acc4.x * ctxq.x + acc4.y * ctxq.y
            + acc4.z * ctxq.z + acc4.w * ctxq.w;
    #pragma unroll
    for (int off = 16; off > 0; off >>= 1)
        s += __shfl_xor_sync(FULL, s, off);    // full sum in ALL lanes

    float val = s + bias;

    // 4 x STG.256, warp-contiguous 1KB per instruction, 32B-aligned.
    float* base = out + (size_t)blockIdx.x * FLOATS_PER_BLOCK_
                      + (unsigned)threadIdx.x * 8u;
    #pragma unroll
    for (int k = 0; k < F8_PER_THREAD_; ++k)
        stg256(base + k * (TPB_ * 8), val);
}

extern "C" void kernel_launch(void* const* d_in, const int* in_sizes, int n_in,
                              void* d_out, int out_size) {
    // metadata order: x, context, Wq, Wk, Wv, Wo, bo
    const float* context = (const float*)d_in[1];
    const float* Wv      = (const float*)d_in[4];
    const float* Wo      = (const float*)d_in[5];
    const float* bo      = (const float*)d_in[6];

    // out_size = 134,217,728 floats -> 16384 blocks x 8192 floats, exact
    int blocks = out_size / FLOATS_PER_BLOCK_;   // 16384
    fused_fill_kernel<<<blocks, TPB_>>>((float*)d_out, context, Wv, Wo, bo);
}

// round 14
// speedup vs baseline: 1.0076x; 1.0021x over previous
#include <cuda_runtime.h>

// ChunkedValueCrossAttn: softmax over a single context token == 1.0, so
// y[b,c,h,w] = (Wo @ (Wv @ context[b]))[c] + bo[c] — a constant per (b,c)
// broadcast over HxW. x/Wq/Wk are dead inputs.
//
// out: [2, 64, 1024, 1024] f32 = 536.9 MB write-only -> HBM store-bound.
//
// Round-12 prologue (best kernel, 74.02us: barrier-free warp-redundant
// constant via y = bo[c] + (Wo[c,:] @ Wv) . ctx, coalesced loads, one
// 5-shfl butterfly) with the last unprobed store shape: 32768 blocks x
// 4 f4/thread (16KB/block). Measured grid curve: 1024:86.7 / 4096:77.8 /
// 16384:74.2 / 131072:78.1 — probing between the two best points for
// finer tail granularity + deeper block backfill.

#define B_       2
#define CQ_      64
#define INNER_   32
#define CTX_     16
#define TPB_     256
#define F4_PER_THREAD_ 4
#define F4_PER_BLOCK_  (TPB_ * F4_PER_THREAD_)   // 1024 float4 = 16KB
// 2^18 f4 per slab / 1024 = 256 blocks per slab

__global__ void __launch_bounds__(TPB_) fused_fill_kernel(
        float4* __restrict__ out,
        const float* __restrict__ context,
        const float* __restrict__ Wv,
        const float* __restrict__ Wo,
        const float* __restrict__ bo) {
    unsigned int slab = blockIdx.x >> 8;       // 256 blocks per slab
    unsigned int b = slab >> 6;                // batch index
    unsigned int c = slab & 63u;               // channel index

    const unsigned FULL = 0xFFFFFFFFu;
    int l = threadIdx.x & 31;

    // ctx quarter for this lane: context[b] is 16 floats = 4 float4.
    float4 ctxq = ((const float4*)context)[b * 4 + (l & 3)];
    float wo_l  = Wo[c * INNER_ + l];          // lane l holds Wo[c,l], coalesced
    float bias  = bo[c];                       // uniform broadcast

    // Wv: 32 rows x 16 floats = 128 float4. Iter t, lane l loads float4
    // idx = 32t+l -> row 8t+(l>>2), quarter l&3. Coalesced 512B per iter.
    const float4* Wv4 = (const float4*)Wv;
    float4 acc4 = make_float4(0.f, 0.f, 0.f, 0.f);
    #pragma unroll
    for (int t = 0; t < 4; ++t) {
        float4 w  = Wv4[t * 32 + l];
        float woc = __shfl_sync(FULL, wo_l, 8 * t + (l >> 2));
        acc4.x += woc * w.x;
        acc4.y += woc * w.y;
        acc4.z += woc * w.z;
        acc4.w += woc * w.w;
    }

    // Per-lane partial covers (rows 8t+(l>>2), quarter l&3) exactly once
    // across the warp -> ONE butterfly finishes the double sum.
    float s = acc4.x * ctxq.x + acc4.y * ctxq.y
            + acc4.z * ctxq.z + acc4.w * ctxq.w;
    #pragma unroll
    for (int off = 16; off > 0; off >>= 1)
        s += __shfl_xor_sync(FULL, s, off);    // full sum in ALL lanes

    float val = s + bias;

    float4 f = make_float4(val, val, val, val);
    unsigned int base = blockIdx.x * (unsigned)F4_PER_BLOCK_ + threadIdx.x;
    #pragma unroll
    for (int k = 0; k < F4_PER_THREAD_; ++k)
        out[base + k * (unsigned)TPB_] = f;
}

extern "C" void kernel_launch(void* const* d_in, const int* in_sizes, int n_in,
                              void* d_out, int out_size) {
    // metadata order: x, context, Wq, Wk, Wv, Wo, bo
    const float* context = (const float*)d_in[1];
    const float* Wv      = (const float*)d_in[4];
    const float* Wo      = (const float*)d_in[5];
    const float* bo      = (const float*)d_in[6];

    // out_size = 134,217,728 floats = 33,554,432 float4 -> 32768 blocks exact
    int n4 = out_size / 4;
    int blocks = n4 / F4_PER_BLOCK_;   // 32768
    fused_fill_kernel<<<blocks, TPB_>>>((float4*)d_out, context, Wv, Wo, bo);
}